// round 15
// baseline (speedup 1.0000x reference)
#include <cuda_runtime.h>
#include <cuda_fp16.h>
#include <cstdint>

// Problem constants
#define BATCH    8
#define NHEADS   8
#define DHEAD    64
#define SEQ      1024
#define BM       64      // q rows per CTA (4 warps x 16)
#define BN       64      // k cols per inner tile
#define NTHREADS 128
#define NKT      (SEQ / BN)   // 16
#define LDQ      64      // halves per smem row of sQ (no pad; one-time aq build)
#define TILE_W   2048    // words per K or V tile (64 rows x 32 words, XOR-swizzled chunks)
#define K_OFF_W(s) ((s) * TILE_W)
#define V_OFF_W(s) (4 * TILE_W + (s) * TILE_W)
#define Q_OFF_W    V_OFF_W(3)             // sQ (2048 words) aliases V stage 3 exactly
#define SMEM_BYTES (8 * TILE_W * 4)       // 65536 -> 3 CTAs/SM (192KB)
#define QSCALE   (0.125f * 1.44269504089f)   // fold 1/sqrt(d) AND log2(e) into Q
#define HONES    0x3C003C00u                 // fp16 (1.0, 1.0)

// ---- Device-global scratch ----
// K,V fp16 in NATURAL [bh][dd][t] layout, t-pairs packed in words:
//   word (bh, dd, w) = ( X[bh][dd][2w], X[bh][dd][2w+1] ),  512 words per row
__device__ uint32_t g_maskbits[BATCH * SEQ * (SEQ / 32)];                 // 1 MB
__device__ uint32_t g_k16[(size_t)BATCH * NHEADS * DHEAD * (SEQ / 2)];    // 8 MB
__device__ uint32_t g_v16[(size_t)BATCH * NHEADS * DHEAD * (SEQ / 2)];    // 8 MB

__device__ __forceinline__ uint32_t f2h2(float x, float y) {
    __half2 h = __floats2half2_rn(x, y);
    return *reinterpret_cast<uint32_t*>(&h);
}
__device__ __forceinline__ uint32_t packh(__half lo, __half hi) {
    return ((uint32_t)__half_as_ushort(hi) << 16) | (uint32_t)__half_as_ushort(lo);
}
__device__ __forceinline__ float ex2(float x) {
    float r;
    asm("ex2.approx.ftz.f32 %0, %1;" : "=f"(r) : "f"(x));
    return r;
}
__device__ __forceinline__ void mma16816(float* d, const uint32_t* a, uint32_t b0, uint32_t b1) {
    asm volatile(
        "mma.sync.aligned.m16n8k16.row.col.f32.f16.f16.f32 "
        "{%0,%1,%2,%3}, {%4,%5,%6,%7}, {%8,%9}, {%0,%1,%2,%3};\n"
        : "+f"(d[0]), "+f"(d[1]), "+f"(d[2]), "+f"(d[3])
        : "r"(a[0]), "r"(a[1]), "r"(a[2]), "r"(a[3]), "r"(b0), "r"(b1));
}
__device__ __forceinline__ void ldsm4(uint32_t& r0, uint32_t& r1, uint32_t& r2, uint32_t& r3,
                                      uint32_t addr) {
    asm volatile("ldmatrix.sync.aligned.m8n8.x4.shared.b16 {%0,%1,%2,%3}, [%4];"
                 : "=r"(r0), "=r"(r1), "=r"(r2), "=r"(r3) : "r"(addr));
}
__device__ __forceinline__ void ldsm4t(uint32_t& r0, uint32_t& r1, uint32_t& r2, uint32_t& r3,
                                       uint32_t addr) {
    asm volatile("ldmatrix.sync.aligned.m8n8.x4.trans.shared.b16 {%0,%1,%2,%3}, [%4];"
                 : "=r"(r0), "=r"(r1), "=r"(r2), "=r"(r3) : "r"(addr));
}
__device__ __forceinline__ void cp16(uint32_t dst, const void* src) {
    asm volatile("cp.async.cg.shared.global [%0], [%1], 16;\n" :: "r"(dst), "l"(src));
}
__device__ __forceinline__ float4 ldcs4(const float* p) {
    float4 f;
    asm("ld.global.cs.v4.f32 {%0,%1,%2,%3}, [%4];"
        : "=f"(f.x), "=f"(f.y), "=f"(f.z), "=f"(f.w) : "l"(p));
    return f;
}

// ---- Fused pre-pass (ALL accesses warp-coalesced; no smem transpose) ----
#define MASK_BLOCKS (BATCH * SEQ * SEQ / 8192)            // 1024
#define RP_BLOCKS   (BATCH * NHEADS * DHEAD / 2)          // 2048 per tensor
#define PREP_BLOCKS (MASK_BLOCKS + 2 * RP_BLOCKS)         // 5120

__global__ void prep_kernel(const float* __restrict__ mask,
                            const float* __restrict__ k,
                            const float* __restrict__ v) {
    const int b = blockIdx.x;
    const int t = threadIdx.x;   // 256 threads
    if (b < MASK_BLOCKS) {
        __shared__ uint8_t nib[2048];
        const float4* src = reinterpret_cast<const float4*>(mask) + (size_t)b * 2048;
        #pragma unroll
        for (int u = 0; u < 8; u++) {
            float4 f = ldcs4(reinterpret_cast<const float*>(src + u * 256 + t));   // coalesced
            nib[u * 256 + t] = (uint8_t)((f.x != 0.f) | ((f.y != 0.f) << 1)
                                       | ((f.z != 0.f) << 2) | ((f.w != 0.f) << 3));
        }
        __syncthreads();
        uint2 p = *reinterpret_cast<const uint2*>(nib + 8 * t);
        uint32_t x = p.x & 0x0F0F0F0Fu;
        x |= x >> 4;  x &= 0x00FF00FFu;  x |= x >> 8;  x &= 0xFFFFu;
        uint32_t y = p.y & 0x0F0F0F0Fu;
        y |= y >> 4;  y &= 0x00FF00FFu;  y |= y >> 8;  y &= 0xFFFFu;
        g_maskbits[b * 256 + t] = x | (y << 16);
    } else {
        // K or V: 2 rows per block, thread j packs 8 consecutive floats -> 4 words
        const bool isK = (b < MASK_BLOCKS + RP_BLOCKS);
        const int idx = b - (isK ? MASK_BLOCKS : (MASK_BLOCKS + RP_BLOCKS));
        const int rg  = idx * 2 + (t >> 7);    // global row (bh*64 + dd)
        const int j   = t & 127;
        const float* src = (isK ? k : v) + (size_t)rg * SEQ + 8 * j;
        float4 fa = ldcs4(src);                // coalesced
        float4 fb = ldcs4(src + 4);
        uint4 w;
        w.x = f2h2(fa.x, fa.y);
        w.y = f2h2(fa.z, fa.w);
        w.z = f2h2(fb.x, fb.y);
        w.w = f2h2(fb.z, fb.w);
        uint32_t* dst = (isK ? g_k16 : g_v16) + (size_t)rg * (SEQ / 2) + 4 * j;
        *reinterpret_cast<uint4*>(dst) = w;
    }
}

__global__ __launch_bounds__(NTHREADS, 3)
void mha_flash_kernel(const float* __restrict__ q, float* __restrict__ out) {
    extern __shared__ float smem[];
    __half* sQ = reinterpret_cast<__half*>(smem + Q_OFF_W);
    const uint32_t smem_b = (uint32_t)__cvta_generic_to_shared(smem);

    const int qt    = blockIdx.x;   // 0..15
    const int bh    = blockIdx.y;   // 0..63
    const int batch = bh >> 3;
    const float*    qb    = q + (size_t)bh * (DHEAD * SEQ);
    const uint32_t* gk    = g_k16 + (size_t)bh * DHEAD * (SEQ / 2);
    const uint32_t* gv    = g_v16 + (size_t)bh * DHEAD * (SEQ / 2);
    const uint32_t* mbits = g_maskbits + (size_t)batch * SEQ * (SEQ / 32);
    float*          ob    = out + (size_t)bh * (DHEAD * SEQ);

    const int tid  = threadIdx.x;
    const int warp = tid >> 5;
    const int lane = tid & 31;
    const int g    = lane >> 2;   // 0..7
    const int c4   = lane & 3;    // 0..3
    // ldmatrix lane decomposition
    const int rl  = lane & 7;
    const int mb0 = (lane >> 3) & 1;
    const int mb1 = lane >> 4;
    const uint32_t krow = (uint32_t)(8 * mb0 + rl) * 128;   // K: dd = 16kk + 8*mb0 + rl
    const uint32_t vrow = (uint32_t)(8 * mb1 + rl) * 128;   // V: dd = 16jp + 8*mb1 + rl
    // Precomputed XOR chunk offsets (shared by K and V LDSM addressing)
    uint32_t xoff[8];
    #pragma unroll
    for (int c = 0; c < 8; c++) xoff[c] = (uint32_t)((c ^ rl) << 4);

    const int t0 = qt * BM;

    // ---- Load Q tile: gmem [dd][t] fp32 -> smem fp16, scale = 0.125*log2(e) ----
    #pragma unroll
    for (int i = tid; i < DHEAD * (BM / 2); i += NTHREADS) {
        int dd = i >> 5;
        int t2 = i & 31;
        float2 val = *reinterpret_cast<const float2*>(qb + (size_t)dd * SEQ + t0 + 2 * t2);
        *reinterpret_cast<__half2*>(&sQ[dd * LDQ + 2 * t2]) =
            __floats2half2_rn(val.x * QSCALE, val.y * QSCALE);
    }
    __syncthreads();

    // ---- Q A-fragments, registers for whole loop (one-time; conflicts OK) ----
    const int r0 = warp * 16 + g;
    const int r8 = r0 + 8;
    uint32_t aq[4][4];
    #pragma unroll
    for (int kk = 0; kk < 4; kk++) {
        int col = 16 * kk + 2 * c4;
        aq[kk][0] = packh(sQ[(col    ) * LDQ + r0], sQ[(col + 1) * LDQ + r0]);
        aq[kk][1] = packh(sQ[(col    ) * LDQ + r8], sQ[(col + 1) * LDQ + r8]);
        aq[kk][2] = packh(sQ[(col + 8) * LDQ + r0], sQ[(col + 9) * LDQ + r0]);
        aq[kk][3] = packh(sQ[(col + 8) * LDQ + r8], sQ[(col + 9) * LDQ + r8]);
    }
    // All threads done reading sQ before issue_tile(3) overwrites V stage 3 (aliased).
    __syncthreads();

    // ---- cp.async: natural-layout tiles, XOR-swizzled chunk destinations ----
    const int      crow = tid >> 3;                    // 0..15
    const uint32_t ccbx = (uint32_t)((tid & 7) ^ (crow & 7));   // const per thread
    auto issue_tile = [&](int kt) {
        if (kt < NKT) {
            const int st = kt & 3;
            const uint32_t kdst = smem_b + K_OFF_W(st) * 4 + ccbx * 16;
            const uint32_t vdst = smem_b + V_OFF_W(st) * 4 + ccbx * 16;
            const uint32_t* ks = gk + kt * (BN / 2) + (tid & 7) * 4;
            const uint32_t* vs = gv + kt * (BN / 2) + (tid & 7) * 4;
            #pragma unroll
            for (int u = 0; u < 4; u++) {
                int row = crow + 16 * u;               // dd
                cp16(kdst + (uint32_t)row * 128, ks + (size_t)row * (SEQ / 2));
                cp16(vdst + (uint32_t)row * 128, vs + (size_t)row * (SEQ / 2));
            }
        }
        asm volatile("cp.async.commit_group;\n");
    };

    issue_tile(0);
    issue_tile(1);
    issue_tile(2);
    // stage 3 (aliases sQ) first written by issue_tile(3) AFTER kt=0 top barrier

    // ---- State: no online max; l via ones-MMA ----
    float lacc[4] = {0.f, 0.f, 0.f, 0.f};
    float o[8][4];
    #pragma unroll
    for (int j = 0; j < 8; j++) { o[j][0] = 0.f; o[j][1] = 0.f; o[j][2] = 0.f; o[j][3] = 0.f; }

    const int qr0 = t0 + r0;
    const int qr8 = t0 + r8;

    for (int kt = 0; kt < NKT; kt++) {
        const int st = kt & 3;
        asm volatile("cp.async.wait_group 2;\n" ::: "memory");
        __syncthreads();

        // ---- Packed mask bits (2x LDG.64, L2-resident, broadcast across c4) ----
        uint2 wm0 = *reinterpret_cast<const uint2*>(mbits + (size_t)qr0 * 32 + 2 * kt);
        uint2 wm8 = *reinterpret_cast<const uint2*>(mbits + (size_t)qr8 * 32 + 2 * kt);

        // ---- Refill freed stage for kt+3 (async) ----
        issue_tile(kt + 3);

        // ---- Scores: S = Q @ K^T via ldmatrix.trans on natural K tiles ----
        const uint32_t kbase = smem_b + K_OFF_W(st) * 4 + krow;
        float s[8][4];
        #pragma unroll
        for (int j = 0; j < 8; j++) { s[j][0] = 0.f; s[j][1] = 0.f; s[j][2] = 0.f; s[j][3] = 0.f; }

        #pragma unroll
        for (int kk = 0; kk < 4; kk++) {
            #pragma unroll
            for (int jp = 0; jp < 4; jp++) {
                uint32_t b0, b1, b2, b3;
                uint32_t addr = kbase + (uint32_t)kk * 2048 + xoff[2 * jp + mb1];
                ldsm4t(b0, b1, b2, b3, addr);
                mma16816(s[2 * jp    ], aq[kk], b0, b1);
                mma16816(s[2 * jp + 1], aq[kk], b2, b3);
            }
        }

        // ---- Mask + exp2 + P pack ----
        uint32_t ap[4][4];
        #pragma unroll
        for (int j = 0; j < 8; j++) {
            uint32_t w0 = (j < 4) ? wm0.x : wm0.y;
            uint32_t w8 = (j < 4) ? wm8.x : wm8.y;
            int bp = 8 * (j & 3) + 2 * c4;
            uint32_t b0 = w0 >> bp;
            uint32_t b8 = w8 >> bp;
            float p0 = (b0 & 1u) ? 0.f : ex2(s[j][0]);
            float p1 = (b0 & 2u) ? 0.f : ex2(s[j][1]);
            float p2 = (b8 & 1u) ? 0.f : ex2(s[j][2]);
            float p3 = (b8 & 2u) ? 0.f : ex2(s[j][3]);
            ap[j >> 1][2 * (j & 1)    ] = f2h2(p0, p1);
            ap[j >> 1][2 * (j & 1) + 1] = f2h2(p2, p3);
        }

        // ---- l += P @ ones ----
        #pragma unroll
        for (int kk = 0; kk < 4; kk++)
            mma16816(lacc, ap[kk], HONES, HONES);

        // ---- O += P @ V via ldmatrix (non-trans) on natural V tiles ----
        const uint32_t vbase = smem_b + V_OFF_W(st) * 4 + vrow;
        #pragma unroll
        for (int kk = 0; kk < 4; kk++) {
            #pragma unroll
            for (int jp = 0; jp < 4; jp++) {
                uint32_t b0, b1, b2, b3;
                uint32_t addr = vbase + (uint32_t)jp * 2048 + xoff[2 * kk + mb0];
                ldsm4(b0, b1, b2, b3, addr);
                mma16816(o[2 * jp    ], ap[kk], b0, b1);
                mma16816(o[2 * jp + 1], ap[kk], b2, b3);
            }
        }
        // single barrier per kt (top of loop)
    }

    // ---- Epilogue: out = o / l ----
    float il0 = 1.f / lacc[0];
    float il8 = 1.f / lacc[2];
    #pragma unroll
    for (int j = 0; j < 8; j++) {
        int dd = 8 * j + 2 * c4;
        ob[(size_t)(dd    ) * SEQ + qr0] = o[j][0] * il0;
        ob[(size_t)(dd + 1) * SEQ + qr0] = o[j][1] * il0;
        ob[(size_t)(dd    ) * SEQ + qr8] = o[j][2] * il8;
        ob[(size_t)(dd + 1) * SEQ + qr8] = o[j][3] * il8;
    }
}

extern "C" void kernel_launch(void* const* d_in, const int* in_sizes, int n_in,
                              void* d_out, int out_size) {
    const float* q    = (const float*)d_in[0];
    const float* k    = (const float*)d_in[1];
    const float* v    = (const float*)d_in[2];
    const float* mask = (const float*)d_in[3];
    float* out = (float*)d_out;

    cudaFuncSetAttribute(mha_flash_kernel,
                         cudaFuncAttributeMaxDynamicSharedMemorySize, SMEM_BYTES);

    prep_kernel<<<PREP_BLOCKS, 256>>>(mask, k, v);

    dim3 grid(SEQ / BM, BATCH * NHEADS);   // (16, 64)
    dim3 block(NTHREADS);
    mha_flash_kernel<<<grid, block, SMEM_BYTES>>>(q, out);
}

// round 16
// speedup vs baseline: 1.0315x; 1.0315x over previous
#include <cuda_runtime.h>
#include <cuda_fp16.h>
#include <cstdint>

// Problem constants
#define BATCH    8
#define NHEADS   8
#define DHEAD    64
#define SEQ      1024
#define BM       64      // q rows per CTA (4 warps x 16)
#define BN       64      // k cols per inner tile
#define NTHREADS 128
#define NKT      (SEQ / BN)   // 16
#define LDQ      64      // halves per smem row of sQ (no pad; one-time aq build)
#define TILE_W   2048    // words per K or V tile (64 rows x 32 words, XOR-swizzled chunks)
#define K_OFF_W(s) ((s) * TILE_W)
#define V_OFF_W(s) (3 * TILE_W + (s) * TILE_W)
#define Q_OFF_W    V_OFF_W(2)             // sQ (2048 words) aliases V stage 2 exactly
#define SMEM_BYTES (6 * TILE_W * 4)       // 49152 -> 4 CTAs/SM
#define QSCALE   (0.125f * 1.44269504089f)   // fold 1/sqrt(d) AND log2(e) into Q
#define HONES    0x3C003C00u                 // fp16 (1.0, 1.0)

// ---- Device-global scratch ----
// K,V fp16 in NATURAL [bh][dd][t] layout, t-pairs packed in words:
//   word (bh, dd, w) = ( X[bh][dd][2w], X[bh][dd][2w+1] ),  512 words per row
__device__ uint32_t g_maskbits[BATCH * SEQ * (SEQ / 32)];                 // 1 MB
__device__ uint32_t g_k16[(size_t)BATCH * NHEADS * DHEAD * (SEQ / 2)];    // 8 MB
__device__ uint32_t g_v16[(size_t)BATCH * NHEADS * DHEAD * (SEQ / 2)];    // 8 MB

__device__ __forceinline__ uint32_t f2h2(float x, float y) {
    __half2 h = __floats2half2_rn(x, y);
    return *reinterpret_cast<uint32_t*>(&h);
}
__device__ __forceinline__ uint32_t packh(__half lo, __half hi) {
    return ((uint32_t)__half_as_ushort(hi) << 16) | (uint32_t)__half_as_ushort(lo);
}
__device__ __forceinline__ uint32_t h2ex2(uint32_t x) {
    uint32_t r;
    asm("ex2.approx.f16x2 %0, %1;" : "=r"(r) : "r"(x));
    return r;
}
__device__ __forceinline__ void mma16816(float* d, const uint32_t* a, uint32_t b0, uint32_t b1) {
    asm volatile(
        "mma.sync.aligned.m16n8k16.row.col.f32.f16.f16.f32 "
        "{%0,%1,%2,%3}, {%4,%5,%6,%7}, {%8,%9}, {%0,%1,%2,%3};\n"
        : "+f"(d[0]), "+f"(d[1]), "+f"(d[2]), "+f"(d[3])
        : "r"(a[0]), "r"(a[1]), "r"(a[2]), "r"(a[3]), "r"(b0), "r"(b1));
}
__device__ __forceinline__ void ldsm4(uint32_t& r0, uint32_t& r1, uint32_t& r2, uint32_t& r3,
                                      uint32_t addr) {
    asm volatile("ldmatrix.sync.aligned.m8n8.x4.shared.b16 {%0,%1,%2,%3}, [%4];"
                 : "=r"(r0), "=r"(r1), "=r"(r2), "=r"(r3) : "r"(addr));
}
__device__ __forceinline__ void ldsm4t(uint32_t& r0, uint32_t& r1, uint32_t& r2, uint32_t& r3,
                                       uint32_t addr) {
    asm volatile("ldmatrix.sync.aligned.m8n8.x4.trans.shared.b16 {%0,%1,%2,%3}, [%4];"
                 : "=r"(r0), "=r"(r1), "=r"(r2), "=r"(r3) : "r"(addr));
}
__device__ __forceinline__ void cp16(uint32_t dst, const void* src) {
    asm volatile("cp.async.cg.shared.global [%0], [%1], 16;\n" :: "r"(dst), "l"(src));
}
__device__ __forceinline__ float4 ldcs4(const float* p) {
    float4 f;
    asm("ld.global.cs.v4.f32 {%0,%1,%2,%3}, [%4];"
        : "=f"(f.x), "=f"(f.y), "=f"(f.z), "=f"(f.w) : "l"(p));
    return f;
}

// ---- Fused pre-pass (ALL accesses warp-coalesced; .cs streaming) ----
#define MASK_BLOCKS (BATCH * SEQ * SEQ / 8192)            // 1024
#define RP_BLOCKS   (BATCH * NHEADS * DHEAD / 2)          // 2048 per tensor
#define PREP_BLOCKS (MASK_BLOCKS + 2 * RP_BLOCKS)         // 5120

__global__ void prep_kernel(const float* __restrict__ mask,
                            const float* __restrict__ k,
                            const float* __restrict__ v) {
    const int b = blockIdx.x;
    const int t = threadIdx.x;   // 256 threads
    if (b < MASK_BLOCKS) {
        __shared__ uint8_t nib[2048];
        const float4* src = reinterpret_cast<const float4*>(mask) + (size_t)b * 2048;
        #pragma unroll
        for (int u = 0; u < 8; u++) {
            float4 f = ldcs4(reinterpret_cast<const float*>(src + u * 256 + t));
            nib[u * 256 + t] = (uint8_t)((f.x != 0.f) | ((f.y != 0.f) << 1)
                                       | ((f.z != 0.f) << 2) | ((f.w != 0.f) << 3));
        }
        __syncthreads();
        uint2 p = *reinterpret_cast<const uint2*>(nib + 8 * t);
        uint32_t x = p.x & 0x0F0F0F0Fu;
        x |= x >> 4;  x &= 0x00FF00FFu;  x |= x >> 8;  x &= 0xFFFFu;
        uint32_t y = p.y & 0x0F0F0F0Fu;
        y |= y >> 4;  y &= 0x00FF00FFu;  y |= y >> 8;  y &= 0xFFFFu;
        g_maskbits[b * 256 + t] = x | (y << 16);
    } else {
        const bool isK = (b < MASK_BLOCKS + RP_BLOCKS);
        const int idx = b - (isK ? MASK_BLOCKS : (MASK_BLOCKS + RP_BLOCKS));
        const int rg  = idx * 2 + (t >> 7);    // global row (bh*64 + dd)
        const int j   = t & 127;
        const float* src = (isK ? k : v) + (size_t)rg * SEQ + 8 * j;
        float4 fa = ldcs4(src);
        float4 fb = ldcs4(src + 4);
        uint4 w;
        w.x = f2h2(fa.x, fa.y);
        w.y = f2h2(fa.z, fa.w);
        w.z = f2h2(fb.x, fb.y);
        w.w = f2h2(fb.z, fb.w);
        uint32_t* dst = (isK ? g_k16 : g_v16) + (size_t)rg * (SEQ / 2) + 4 * j;
        *reinterpret_cast<uint4*>(dst) = w;
    }
}

__global__ __launch_bounds__(NTHREADS, 4)
void mha_flash_kernel(const float* __restrict__ q, float* __restrict__ out) {
    extern __shared__ float smem[];
    __half* sQ = reinterpret_cast<__half*>(smem + Q_OFF_W);
    const uint32_t smem_b = (uint32_t)__cvta_generic_to_shared(smem);

    const int qt    = blockIdx.x;   // 0..15
    const int bh    = blockIdx.y;   // 0..63
    const int batch = bh >> 3;
    const float*    qb    = q + (size_t)bh * (DHEAD * SEQ);
    const uint32_t* gk    = g_k16 + (size_t)bh * DHEAD * (SEQ / 2);
    const uint32_t* gv    = g_v16 + (size_t)bh * DHEAD * (SEQ / 2);
    const uint32_t* mbits = g_maskbits + (size_t)batch * SEQ * (SEQ / 32);
    float*          ob    = out + (size_t)bh * (DHEAD * SEQ);

    const int tid  = threadIdx.x;
    const int warp = tid >> 5;
    const int lane = tid & 31;
    const int g    = lane >> 2;   // 0..7
    const int c4   = lane & 3;    // 0..3
    // ldmatrix lane decomposition
    const int rl  = lane & 7;
    const int mb0 = (lane >> 3) & 1;
    const int mb1 = lane >> 4;
    const uint32_t krow = (uint32_t)(8 * mb0 + rl) * 128;   // K: dd = 16kk + 8*mb0 + rl
    const uint32_t vrow = (uint32_t)(8 * mb1 + rl) * 128;   // V: dd = 16jp + 8*mb1 + rl

    const int t0 = qt * BM;

    // ---- Load Q tile: gmem [dd][t] fp32 -> smem fp16, scale = 0.125*log2(e) ----
    #pragma unroll
    for (int i = tid; i < DHEAD * (BM / 2); i += NTHREADS) {
        int dd = i >> 5;
        int t2 = i & 31;
        float2 val = *reinterpret_cast<const float2*>(qb + (size_t)dd * SEQ + t0 + 2 * t2);
        *reinterpret_cast<__half2*>(&sQ[dd * LDQ + 2 * t2]) =
            __floats2half2_rn(val.x * QSCALE, val.y * QSCALE);
    }
    __syncthreads();

    // ---- Q A-fragments, registers for whole loop (one-time; conflicts OK) ----
    const int r0 = warp * 16 + g;
    const int r8 = r0 + 8;
    uint32_t aq[4][4];
    #pragma unroll
    for (int kk = 0; kk < 4; kk++) {
        int col = 16 * kk + 2 * c4;
        aq[kk][0] = packh(sQ[(col    ) * LDQ + r0], sQ[(col + 1) * LDQ + r0]);
        aq[kk][1] = packh(sQ[(col    ) * LDQ + r8], sQ[(col + 1) * LDQ + r8]);
        aq[kk][2] = packh(sQ[(col + 8) * LDQ + r0], sQ[(col + 9) * LDQ + r0]);
        aq[kk][3] = packh(sQ[(col + 8) * LDQ + r8], sQ[(col + 9) * LDQ + r8]);
    }
    // All threads done reading sQ before issue_tile(2) overwrites V stage 2 (aliased).
    __syncthreads();

    // ---- cp.async: natural-layout tiles, XOR-swizzled chunk destinations ----
    const int      crow = tid >> 3;                    // 0..15
    const uint32_t ccbx = (uint32_t)((tid & 7) ^ (crow & 7));   // const per thread
    auto issue_tile = [&](int kt) {
        if (kt < NKT) {
            const int st = kt % 3;
            const uint32_t kdst = smem_b + K_OFF_W(st) * 4 + ccbx * 16;
            const uint32_t vdst = smem_b + V_OFF_W(st) * 4 + ccbx * 16;
            const uint32_t* ks = gk + kt * (BN / 2) + (tid & 7) * 4;
            const uint32_t* vs = gv + kt * (BN / 2) + (tid & 7) * 4;
            #pragma unroll
            for (int u = 0; u < 4; u++) {
                int row = crow + 16 * u;               // dd
                cp16(kdst + (uint32_t)row * 128, ks + (size_t)row * (SEQ / 2));
                cp16(vdst + (uint32_t)row * 128, vs + (size_t)row * (SEQ / 2));
            }
        }
        asm volatile("cp.async.commit_group;\n");
    };

    issue_tile(0);
    issue_tile(1);
    // stage 2 (aliases sQ) first written by issue_tile(2) AFTER kt=0 top barrier

    // ---- State: no online max; l via ones-MMA ----
    float lacc[4] = {0.f, 0.f, 0.f, 0.f};
    float o[8][4];
    #pragma unroll
    for (int j = 0; j < 8; j++) { o[j][0] = 0.f; o[j][1] = 0.f; o[j][2] = 0.f; o[j][3] = 0.f; }

    const int qr0 = t0 + r0;
    const int qr8 = t0 + r8;
    const uint32_t NEGINF2 = 0xFC00FC00u;   // fp16 (-inf, -inf)

    for (int kt = 0; kt < NKT; kt++) {
        const int st = kt % 3;

        // ---- Mask bits hoisted ABOVE the wait: independent of smem stages ----
        uint2 wm0 = *reinterpret_cast<const uint2*>(mbits + (size_t)qr0 * 32 + 2 * kt);
        uint2 wm8 = *reinterpret_cast<const uint2*>(mbits + (size_t)qr8 * 32 + 2 * kt);

        asm volatile("cp.async.wait_group 1;\n" ::: "memory");
        __syncthreads();

        // ---- Refill freed stage for kt+2 (async) ----
        issue_tile(kt + 2);

        // ---- Scores: S = Q @ K^T via ldmatrix.trans on natural K tiles ----
        const uint32_t kbase = smem_b + K_OFF_W(st) * 4 + krow;
        float s[8][4];
        #pragma unroll
        for (int j = 0; j < 8; j++) { s[j][0] = 0.f; s[j][1] = 0.f; s[j][2] = 0.f; s[j][3] = 0.f; }

        #pragma unroll
        for (int kk = 0; kk < 4; kk++) {
            #pragma unroll
            for (int jp = 0; jp < 4; jp++) {
                uint32_t b0, b1, b2, b3;
                uint32_t addr = kbase + (uint32_t)kk * 2048
                              + ((uint32_t)((2 * jp + mb1) ^ rl) << 4);
                ldsm4t(b0, b1, b2, b3, addr);
                mma16816(s[2 * jp    ], aq[kk], b0, b1);
                mma16816(s[2 * jp + 1], aq[kk], b2, b3);
            }
        }

        // ---- Pack to half2, splice fp16 -inf where masked, f16x2 exp2 ----
        uint32_t ap[4][4];
        #pragma unroll
        for (int j = 0; j < 8; j++) {
            uint32_t w0 = (j < 4) ? wm0.x : wm0.y;
            uint32_t w8 = (j < 4) ? wm8.x : wm8.y;
            int bp = 8 * (j & 3) + 2 * c4;
            uint32_t b0 = (w0 >> bp) & 3u;
            uint32_t b8 = (w8 >> bp) & 3u;
            uint32_t m0 = ((b0 & 1u) ? 0x0000FFFFu : 0u) | ((b0 & 2u) ? 0xFFFF0000u : 0u);
            uint32_t m8 = ((b8 & 1u) ? 0x0000FFFFu : 0u) | ((b8 & 2u) ? 0xFFFF0000u : 0u);
            uint32_t hs0 = f2h2(s[j][0], s[j][1]);
            uint32_t hs8 = f2h2(s[j][2], s[j][3]);
            hs0 = (hs0 & ~m0) | (NEGINF2 & m0);   // single LOP3
            hs8 = (hs8 & ~m8) | (NEGINF2 & m8);
            ap[j >> 1][2 * (j & 1)    ] = h2ex2(hs0);   // ex2(-inf) = +0
            ap[j >> 1][2 * (j & 1) + 1] = h2ex2(hs8);
        }

        // ---- l += P @ ones ----
        #pragma unroll
        for (int kk = 0; kk < 4; kk++)
            mma16816(lacc, ap[kk], HONES, HONES);

        // ---- O += P @ V via ldmatrix (non-trans) on natural V tiles ----
        const uint32_t vbase = smem_b + V_OFF_W(st) * 4 + vrow;
        #pragma unroll
        for (int kk = 0; kk < 4; kk++) {
            #pragma unroll
            for (int jp = 0; jp < 4; jp++) {
                uint32_t b0, b1, b2, b3;
                uint32_t addr = vbase + (uint32_t)jp * 2048
                              + ((uint32_t)((2 * kk + mb0) ^ rl) << 4);
                ldsm4(b0, b1, b2, b3, addr);
                mma16816(o[2 * jp    ], ap[kk], b0, b1);
                mma16816(o[2 * jp + 1], ap[kk], b2, b3);
            }
        }
        // single barrier per kt (top of loop)
    }

    // ---- Epilogue: out = o / l ----
    float il0 = 1.f / lacc[0];
    float il8 = 1.f / lacc[2];
    #pragma unroll
    for (int j = 0; j < 8; j++) {
        int dd = 8 * j + 2 * c4;
        ob[(size_t)(dd    ) * SEQ + qr0] = o[j][0] * il0;
        ob[(size_t)(dd + 1) * SEQ + qr0] = o[j][1] * il0;
        ob[(size_t)(dd    ) * SEQ + qr8] = o[j][2] * il8;
        ob[(size_t)(dd + 1) * SEQ + qr8] = o[j][3] * il8;
    }
}

extern "C" void kernel_launch(void* const* d_in, const int* in_sizes, int n_in,
                              void* d_out, int out_size) {
    const float* q    = (const float*)d_in[0];
    const float* k    = (const float*)d_in[1];
    const float* v    = (const float*)d_in[2];
    const float* mask = (const float*)d_in[3];
    float* out = (float*)d_out;

    cudaFuncSetAttribute(mha_flash_kernel,
                         cudaFuncAttributeMaxDynamicSharedMemorySize, SMEM_BYTES);

    prep_kernel<<<PREP_BLOCKS, 256>>>(mask, k, v);

    dim3 grid(SEQ / BM, BATCH * NHEADS);   // (16, 64)
    dim3 block(NTHREADS);
    mha_flash_kernel<<<grid, block, SMEM_BYTES>>>(q, out);
}